// round 15
// baseline (speedup 1.0000x reference)
#include <cuda_runtime.h>
#include <cuda_bf16.h>
#include <cuda_fp8.h>
#include <cstdint>
#include <math.h>

#define BATCH 8
#define SEQ   2048
#define DIM   512
#define BM    128
#define BN    128
#define NKP   4
#define NTILE (SEQ / BM)
#define NBLK  (BATCH * NTILE)
#define NJOBS 136                    // GEMM jobs per batch
#define TPB   (NJOBS + NTILE)        // tickets per batch = 152
#define TOTTICK (TPB * BATCH)        // 1216
#define NPERS 296                    // persistent CTAs (2 per SM)
#define NNORM 148                    // normalizer-role CTAs

#define SCALE8     50.59644256f
#define INV256     0.00390625f
#define SHIFT      10.0f
#define LAMBDA     0.5f

#define RSTRIDE    80
#define CTILE_B    (BM * RSTRIDE)
#define SMEM_TOTAL (8 * CTILE_B)

__device__ uint8_t g_l8[BATCH * SEQ * DIM];
__device__ float g_rse[BATCH][NTILE][9][BM];
__device__ float g_cse[BATCH][NTILE][8][BM];
__device__ float g_cpart[BATCH][NTILE * 2][DIM];
__device__ float g_partials[NBLK];
__device__ int   g_cnt;              // finalize partials done (target NBLK)
__device__ int   g_ticket;
__device__ int   g_exit;             // exited CTAs (target NPERS)
__device__ int   g_ready[BATCH];     // normalized rows per batch
__device__ int   g_fin[BATCH][NTILE];// per-block contributions (target 16)
__device__ int   g_dcnt[BATCH];      // diagonal jobs done (target NTILE)

__device__ __forceinline__ uint32_t smem_u32(const void* p) {
    uint32_t a;
    asm("{ .reg .u64 t; cvta.to.shared.u64 t, %1; cvt.u32.u64 %0, t; }"
        : "=r"(a) : "l"(p));
    return a;
}
__device__ __forceinline__ int ld_acquire(const int* p) {
    int v;
    asm volatile("ld.acquire.gpu.global.b32 %0, [%1];" : "=r"(v) : "l"(p));
    return v;
}
#define CP16(d, s) \
    asm volatile("cp.async.cg.shared.global [%0], [%1], 16;" :: "r"(d), "l"(s))
#define CP_COMMIT() asm volatile("cp.async.commit_group;" ::: "memory")
#define CP_WAIT(n)  asm volatile("cp.async.wait_group %0;" :: "n"(n) : "memory")

__device__ __forceinline__ void ldsm4(uint32_t* r, uint32_t addr) {
    asm volatile("ldmatrix.sync.aligned.m8n8.x4.shared.b16 {%0,%1,%2,%3}, [%4];"
                 : "=r"(r[0]), "=r"(r[1]), "=r"(r[2]), "=r"(r[3]) : "r"(addr));
}
__device__ __forceinline__ void mma16832(float* d, const uint32_t* a,
                                         uint32_t b0, uint32_t b1) {
    asm volatile(
        "mma.sync.aligned.m16n8k32.row.col.f32.e4m3.e4m3.f32 "
        "{%0,%1,%2,%3}, {%4,%5,%6,%7}, {%8,%9}, {%0,%1,%2,%3};"
        : "+f"(d[0]), "+f"(d[1]), "+f"(d[2]), "+f"(d[3])
        : "r"(a[0]), "r"(a[1]), "r"(a[2]), "r"(a[3]), "r"(b0), "r"(b1));
}
__device__ __forceinline__ float fp8_to_f32(uint8_t b) {
    __half_raw h = __nv_cvt_fp8_to_halfraw((__nv_fp8_storage_t)b, __NV_E4M3);
    return __half2float(*reinterpret_cast<__half*>(&h));
}

// ---------------------------------------------------------------------------
// Single persistent kernel: normalize (role A) -> GEMM jobs -> finalize jobs,
// all dependency-tracked with fenced counters; out written by the CTA that
// completes the last finalize partial; counters reset by the last exiter.
// ---------------------------------------------------------------------------
__global__ void __launch_bounds__(256, 2) fused_all_kernel(
        const float* __restrict__ x, float* __restrict__ out) {
    extern __shared__ char smem[];
    const uint32_t sb  = smem_u32(smem);
    const int tid  = threadIdx.x;
    const int wid  = tid >> 5;
    const int lane = tid & 31;
    const int warp_m = wid >> 1;
    const int warp_n = wid & 1;

    const int g    = lane >> 2;
    const int tig  = lane & 3;
    const int lrow = lane & 15;
    const int lsel = (lane >> 4) & 1;

    __shared__ int   job_s;
    __shared__ int   flag_s;
    __shared__ float smc[8][64];
    __shared__ float se_red[8][8][4];
    __shared__ float ws[8];

    // ---------------- role A: normalize ----------------
    if (blockIdx.x < NNORM) {
        const int c = blockIdx.x;
        for (int b = 0; b < BATCH; ++b) {
            for (int idx = c + NNORM * wid; idx < SEQ; idx += NNORM * 8) {
                const int row = b * SEQ + idx;
                const float4* __restrict__ xr =
                    reinterpret_cast<const float4*>(x + (size_t)row * DIM)
                    + lane * 4;
                float4 v[4];
                float ss = 0.f;
                #pragma unroll
                for (int q = 0; q < 4; ++q) {
                    v[q] = xr[q];
                    ss = fmaf(v[q].x, v[q].x, ss);
                    ss = fmaf(v[q].y, v[q].y, ss);
                    ss = fmaf(v[q].z, v[q].z, ss);
                    ss = fmaf(v[q].w, v[q].w, ss);
                }
                #pragma unroll
                for (int o = 16; o > 0; o >>= 1)
                    ss += __shfl_xor_sync(0xffffffffu, ss, o);
                const float inv = SCALE8 / fmaxf(sqrtf(ss), 1e-8f);
                uint32_t w[4];
                #pragma unroll
                for (int q = 0; q < 4; ++q) {
                    const __nv_fp8x2_storage_t p01 = __nv_cvt_float2_to_fp8x2(
                        make_float2(v[q].x * inv, v[q].y * inv),
                        __NV_SATFINITE, __NV_E4M3);
                    const __nv_fp8x2_storage_t p23 = __nv_cvt_float2_to_fp8x2(
                        make_float2(v[q].z * inv, v[q].w * inv),
                        __NV_SATFINITE, __NV_E4M3);
                    w[q] = (uint32_t)p01 | ((uint32_t)p23 << 16);
                }
                uint4 o4;
                o4.x = w[0]; o4.y = w[1]; o4.z = w[2]; o4.w = w[3];
                *reinterpret_cast<uint4*>(
                    g_l8 + (size_t)row * DIM + lane * 16) = o4;
            }
            __syncthreads();
            if (tid == 0) {
                __threadfence();
                const int cnt = (SEQ - 1 - c) / NNORM + 1;
                atomicAdd(&g_ready[b], cnt);
            }
        }
    }

    // ---------------- job loop ----------------
    for (;;) {
        if (tid == 0) job_s = atomicAdd(&g_ticket, 1);
        __syncthreads();
        const int ticket = job_s;
        if (ticket >= TOTTICK) {
            if (tid == 0) {
                const int old = atomicAdd(&g_exit, 1);
                if (old == NPERS - 1) {   // last exiter: reset for graph replay
                    g_ticket = 0; g_exit = 0; g_cnt = 0;
                    #pragma unroll
                    for (int b2 = 0; b2 < BATCH; ++b2) {
                        g_ready[b2] = 0;
                        g_dcnt[b2]  = 0;
                        for (int k2 = 0; k2 < NTILE; ++k2) g_fin[b2][k2] = 0;
                    }
                }
            }
            break;
        }

        const int bi = ticket / TPB;
        const int rr = ticket - bi * TPB;

        if (rr >= NJOBS) {
            // ================= finalize job (b=bi, k=rr-NJOBS) =================
            const int k = rr - NJOBS;
            if (tid == 0) {
                while (ld_acquire(&g_fin[bi][k]) < 16) __nanosleep(64);
                if (k == 0)
                    while (ld_acquire(&g_dcnt[bi]) < NTILE) __nanosleep(64);
            }
            __syncthreads();

            const int r   = tid >> 1;        // row 0..127
            const int sub = tid & 1;
            const int nrow = (k < 8) ? 9 : 8;
            float seT = 0.f;
            #pragma unroll
            for (int u = 0; u < 8; ++u) {
                const int s = sub * 8 + u;   // 0..15
                seT += (s < nrow) ? g_rse[bi][k][s][r]
                                  : g_cse[bi][k][s - nrow][r];
            }
            seT += __shfl_xor_sync(0xffffffffu, seT, 1);

            float contrib = (sub == 0)
                ? (float)(SEQ - 1) * (SHIFT + logf(seT)) : 0.f;

            if (k == 0) {
                // batch analytic-rowsum term, distributed over 256 threads:
                // each owns components tid and tid+256 of c_b.
                float c1 = 0.f, c2 = 0.f;
                #pragma unroll
                for (int p = 0; p < NTILE * 2; ++p) {
                    c1 += g_cpart[bi][p][tid];
                    c2 += g_cpart[bi][p][tid + 256];
                }
                contrib += (SHIFT * (float)SEQ) * (1.0f / 256.0f)
                         - (c1 * c1 + c2 * c2) * INV256;
            }

            #pragma unroll
            for (int o = 2; o < 32; o <<= 1)
                contrib += __shfl_xor_sync(0xffffffffu, contrib, o);
            contrib += __shfl_xor_sync(0xffffffffu, contrib, 1);
            if (lane == 0) ws[wid] = contrib;
            __syncthreads();
            if (tid == 0) {
                float v = 0.f;
                #pragma unroll
                for (int w2 = 0; w2 < 8; ++w2) v += ws[w2];
                g_partials[bi * NTILE + k] = v;
                __threadfence();
                const int old = atomicAdd(&g_cnt, 1);
                flag_s = (old == NBLK - 1) ? 1 : 0;
            }
            __syncthreads();

            if (flag_s) {      // last finalize partial: deterministic final sum
                if (tid < 128) {
                    __threadfence();
                    float v = __ldcg(&g_partials[tid]);
                    #pragma unroll
                    for (int o = 16; o > 0; o >>= 1)
                        v += __shfl_xor_sync(0xffffffffu, v, o);
                    if ((tid & 31) == 0) ws[tid >> 5] = v;
                }
                __syncthreads();
                if (tid == 0)
                    out[0] = (ws[0] + ws[1] + ws[2] + ws[3])
                           * (LAMBDA / ((float)BATCH * (float)SEQ * (float)SEQ));
            }
            __syncthreads();   // protect ws/flag_s before next ticket
            continue;
        }

        // ================= GEMM job =================
        const int jx = rr;
        int it, m;
        if (jx < 72) { it = jx / 9; m = jx % 9; }
        else { const int t2 = jx - 72; it = 8 + t2 / 8; m = t2 % 8; }
        const int j = (it + m) & 15;

        if (tid == 0)
            while (ld_acquire(&g_ready[bi]) < SEQ) __nanosleep(64);
        __syncthreads();

        const uint8_t* __restrict__ base = g_l8 + (size_t)bi * SEQ * DIM;
        const uint8_t* __restrict__ Ab   = base + (size_t)(it * BM) * DIM;
        const uint8_t* __restrict__ Bb   = base + (size_t)(j * BN) * DIM;

        auto load_stage = [&](int stage, int kp) {
            const uint32_t sbase = sb + stage * 4 * CTILE_B;
            #pragma unroll
            for (int u = 0; u < 8; ++u) {
                const int p  = tid + u * 256;
                const int ch = p >> 9;
                const int rem = p & 511;
                const int r = rem >> 2, c = rem & 3;
                const uint8_t* src = (ch < 2 ? Ab : Bb)
                    + (size_t)r * DIM + kp * 128 + (ch & 1) * 64 + c * 16;
                CP16(sbase + ch * CTILE_B + r * RSTRIDE + c * 16, src);
            }
            CP_COMMIT();
        };

        load_stage(0, 0);

        float acc[2][8][4];
        #pragma unroll
        for (int mt = 0; mt < 2; ++mt)
            #pragma unroll
            for (int nt = 0; nt < 8; ++nt)
                #pragma unroll
                for (int i = 0; i < 4; ++i) acc[mt][nt][i] = 0.f;

        for (int kp = 0; kp < NKP; ++kp) {
            if (kp + 1 < NKP) {
                load_stage((kp + 1) & 1, kp + 1);
                CP_WAIT(1);
            } else {
                CP_WAIT(0);
            }
            __syncthreads();

            #pragma unroll
            for (int cc = 0; cc < 2; ++cc) {
                const uint32_t abase = sb + ((kp & 1) * 4 + cc) * CTILE_B;
                const uint32_t bbase = sb + ((kp & 1) * 4 + 2 + cc) * CTILE_B;
                #pragma unroll
                for (int ks = 0; ks < 2; ++ks) {
                    uint32_t af[2][4];
                    #pragma unroll
                    for (int mt = 0; mt < 2; ++mt)
                        ldsm4(af[mt], abase
                              + (warp_m * 32 + mt * 16 + lrow) * RSTRIDE
                              + ks * 32 + lsel * 16);
                    uint32_t bx[4][4];
                    #pragma unroll
                    for (int q = 0; q < 4; ++q)
                        ldsm4(bx[q], bbase
                              + (warp_n * 64 + q * 16 + lrow) * RSTRIDE
                              + ks * 32 + lsel * 16);
                    #pragma unroll
                    for (int mt = 0; mt < 2; ++mt)
                        #pragma unroll
                        for (int nt = 0; nt < 8; ++nt) {
                            const int q = nt >> 1, e = nt & 1;
                            mma16832(acc[mt][nt], af[mt], bx[q][e], bx[q][e + 2]);
                        }
                }
            }

            // fused column-sum partials (diagonal jobs only)
            if (m == 0) {
                const int half = tid >> 7;
                const int col  = tid & 127;
                const size_t off = (size_t)((kp & 1) * 4 + (col >> 6)) * CTILE_B
                                 + (size_t)(half * 64) * RSTRIDE + (col & 63);
                float s = 0.f;
                #pragma unroll 8
                for (int r2 = 0; r2 < 64; ++r2)
                    s += fp8_to_f32((uint8_t)smem[off + (size_t)r2 * RSTRIDE]);
                g_cpart[bi][it * 2 + half][kp * 128 + col] = s;
            }
            __syncthreads();
        }

        // fused two-sided epilogue (sumexp only; v = acc/256)
        float se[4];
        #pragma unroll
        for (int s = 0; s < 4; ++s) se[s] = 0.f;

        if (m == 0) {
            #pragma unroll
            for (int mt = 0; mt < 2; ++mt)
                #pragma unroll
                for (int nt = 0; nt < 8; ++nt)
                    #pragma unroll
                    for (int i = 0; i < 4; ++i) {
                        const int lr = warp_m * 32 + mt * 16 + (i >> 1) * 8 + g;
                        const int lc = warp_n * 64 + nt * 8 + tig * 2 + (i & 1);
                        if (lr != lc)
                            se[mt * 2 + (i >> 1)] +=
                                __expf(fmaf(acc[mt][nt][i], INV256, -SHIFT));
                    }
        } else {
            float cse[16];
            #pragma unroll
            for (int q = 0; q < 16; ++q) cse[q] = 0.f;
            #pragma unroll
            for (int mt = 0; mt < 2; ++mt)
                #pragma unroll
                for (int nt = 0; nt < 8; ++nt)
                    #pragma unroll
                    for (int i = 0; i < 4; ++i) {
                        const float e =
                            __expf(fmaf(acc[mt][nt][i], INV256, -SHIFT));
                        se[mt * 2 + (i >> 1)] += e;
                        cse[nt * 2 + (i & 1)] += e;
                    }
            #pragma unroll
            for (int q = 0; q < 16; ++q) {
                #pragma unroll
                for (int o = 4; o < 32; o <<= 1)
                    cse[q] += __shfl_xor_sync(0xffffffffu, cse[q], o);
            }
            if (lane < 4) {
                #pragma unroll
                for (int nt = 0; nt < 8; ++nt)
                    #pragma unroll
                    for (int b2 = 0; b2 < 2; ++b2)
                        smc[wid][nt * 8 + lane * 2 + b2] = cse[nt * 2 + b2];
            }
        }

        #pragma unroll
        for (int s = 0; s < 4; ++s) {
            #pragma unroll
            for (int o = 1; o < 4; o <<= 1)
                se[s] += __shfl_xor_sync(0xffffffffu, se[s], o);
        }
        if (tig == 0) {
            #pragma unroll
            for (int s = 0; s < 4; ++s) se_red[wid][g][s] = se[s];
        }
        __syncthreads();

        if (tid < BM) {
            const int wm = tid >> 5;
            const int gg = (tid >> 2) & 7;
            const int ss = tid & 3;
            const int row = wm * 32 + (ss >> 1) * 16 + (ss & 1) * 8 + gg;
            g_rse[bi][it][m][row] =
                se_red[wm * 2][gg][ss] + se_red[wm * 2 + 1][gg][ss];
        } else if (m > 0) {
            const int t2 = tid - BM;
            const int wn = t2 >> 6, lc = t2 & 63;
            float cs = 0.f;
            #pragma unroll
            for (int wm = 0; wm < 4; ++wm) cs += smc[wm * 2 + wn][lc];
            g_cse[bi][j][m - 1][t2] = cs;
        }
        __syncthreads();

        // publish contributions (fenced)
        if (tid == 0) {
            __threadfence();
            atomicAdd(&g_fin[bi][it], 1);
            if (m > 0) atomicAdd(&g_fin[bi][j], 1);
            else       atomicAdd(&g_dcnt[bi], 1);
        }
    }
}

extern "C" void kernel_launch(void* const* d_in, const int* in_sizes, int n_in,
                              void* d_out, int out_size) {
    (void)in_sizes; (void)n_in; (void)out_size;
    const float* x = (const float*)d_in[0];
    float* out = (float*)d_out;

    cudaFuncSetAttribute(fused_all_kernel,
                         cudaFuncAttributeMaxDynamicSharedMemorySize, SMEM_TOTAL);

    fused_all_kernel<<<NPERS, 256, SMEM_TOTAL>>>(x, out);
}

// round 16
// speedup vs baseline: 1.0870x; 1.0870x over previous
#include <cuda_runtime.h>
#include <cuda_bf16.h>
#include <cuda_fp8.h>
#include <cstdint>
#include <math.h>

#define BATCH 8
#define SEQ   2048
#define DIM   512
#define BM    128
#define BN    128
#define NKP   4
#define NTILE (SEQ / BM)
#define NBLK  (BATCH * NTILE)
#define NJOBS 136                    // GEMM jobs per batch
#define TOTJOBS (NJOBS * BATCH)      // 1088
#define TOTTICK (TOTJOBS + NBLK)     // 1216: GEMM tickets then finalize tickets
#define NPERS 296                    // persistent CTAs (2 per SM)
#define NNORM 148                    // normalizer-role CTAs

#define SCALE8     50.59644256f
#define INV256     0.00390625f
#define SHIFT      10.0f
#define LAMBDA     0.5f

#define RSTRIDE    80
#define CTILE_B    (BM * RSTRIDE)
#define SMEM_TOTAL (8 * CTILE_B)

__device__ uint8_t g_l8[BATCH * SEQ * DIM];
__device__ float g_rse[BATCH][NTILE][9][BM];
__device__ float g_cse[BATCH][NTILE][8][BM];
__device__ float g_cpart[BATCH][NTILE * 2][DIM];
__device__ float g_partials[NBLK];
__device__ int   g_cnt;              // finalize partials done (target NBLK)
__device__ int   g_ticket;
__device__ int   g_exit;             // exited CTAs (target NPERS)
__device__ int   g_ready[BATCH];     // normalized rows per batch
__device__ int   g_fin[BATCH][NTILE];// per-block contributions (target 16)
__device__ int   g_dcnt[BATCH];      // diagonal jobs done (target NTILE)

__device__ __forceinline__ uint32_t smem_u32(const void* p) {
    uint32_t a;
    asm("{ .reg .u64 t; cvta.to.shared.u64 t, %1; cvt.u32.u64 %0, t; }"
        : "=r"(a) : "l"(p));
    return a;
}
__device__ __forceinline__ int ld_acquire(const int* p) {
    int v;
    asm volatile("ld.acquire.gpu.global.b32 %0, [%1];" : "=r"(v) : "l"(p));
    return v;
}
#define CP16(d, s) \
    asm volatile("cp.async.cg.shared.global [%0], [%1], 16;" :: "r"(d), "l"(s))
#define CP_COMMIT() asm volatile("cp.async.commit_group;" ::: "memory")
#define CP_WAIT(n)  asm volatile("cp.async.wait_group %0;" :: "n"(n) : "memory")

__device__ __forceinline__ void ldsm4(uint32_t* r, uint32_t addr) {
    asm volatile("ldmatrix.sync.aligned.m8n8.x4.shared.b16 {%0,%1,%2,%3}, [%4];"
                 : "=r"(r[0]), "=r"(r[1]), "=r"(r[2]), "=r"(r[3]) : "r"(addr));
}
__device__ __forceinline__ void mma16832(float* d, const uint32_t* a,
                                         uint32_t b0, uint32_t b1) {
    asm volatile(
        "mma.sync.aligned.m16n8k32.row.col.f32.e4m3.e4m3.f32 "
        "{%0,%1,%2,%3}, {%4,%5,%6,%7}, {%8,%9}, {%0,%1,%2,%3};"
        : "+f"(d[0]), "+f"(d[1]), "+f"(d[2]), "+f"(d[3])
        : "r"(a[0]), "r"(a[1]), "r"(a[2]), "r"(a[3]), "r"(b0), "r"(b1));
}
__device__ __forceinline__ float fp8_to_f32(uint8_t b) {
    __half_raw h = __nv_cvt_fp8_to_halfraw((__nv_fp8_storage_t)b, __NV_E4M3);
    return __half2float(*reinterpret_cast<__half*>(&h));
}

// ---------------------------------------------------------------------------
// Single persistent kernel. Tickets 0..1087: GEMM jobs (batch-major).
// Tickets 1088..1215: finalize jobs (batch-major) — placed at the GLOBAL tail
// so a finalize spin never displaces a runnable GEMM job (round-15 bug).
// ---------------------------------------------------------------------------
__global__ void __launch_bounds__(256, 2) fused_all_kernel(
        const float* __restrict__ x, float* __restrict__ out) {
    extern __shared__ char smem[];
    const uint32_t sb  = smem_u32(smem);
    const int tid  = threadIdx.x;
    const int wid  = tid >> 5;
    const int lane = tid & 31;
    const int warp_m = wid >> 1;
    const int warp_n = wid & 1;

    const int g    = lane >> 2;
    const int tig  = lane & 3;
    const int lrow = lane & 15;
    const int lsel = (lane >> 4) & 1;

    __shared__ int   job_s;
    __shared__ int   flag_s;
    __shared__ float smc[8][64];
    __shared__ float se_red[8][8][4];
    __shared__ float ws[8];

    // ---------------- role A: normalize ----------------
    if (blockIdx.x < NNORM) {
        const int c = blockIdx.x;
        for (int b = 0; b < BATCH; ++b) {
            for (int idx = c + NNORM * wid; idx < SEQ; idx += NNORM * 8) {
                const int row = b * SEQ + idx;
                const float4* __restrict__ xr =
                    reinterpret_cast<const float4*>(x + (size_t)row * DIM)
                    + lane * 4;
                float4 v[4];
                float ss = 0.f;
                #pragma unroll
                for (int q = 0; q < 4; ++q) {
                    v[q] = xr[q];
                    ss = fmaf(v[q].x, v[q].x, ss);
                    ss = fmaf(v[q].y, v[q].y, ss);
                    ss = fmaf(v[q].z, v[q].z, ss);
                    ss = fmaf(v[q].w, v[q].w, ss);
                }
                #pragma unroll
                for (int o = 16; o > 0; o >>= 1)
                    ss += __shfl_xor_sync(0xffffffffu, ss, o);
                const float inv = SCALE8 / fmaxf(sqrtf(ss), 1e-8f);
                uint32_t w[4];
                #pragma unroll
                for (int q = 0; q < 4; ++q) {
                    const __nv_fp8x2_storage_t p01 = __nv_cvt_float2_to_fp8x2(
                        make_float2(v[q].x * inv, v[q].y * inv),
                        __NV_SATFINITE, __NV_E4M3);
                    const __nv_fp8x2_storage_t p23 = __nv_cvt_float2_to_fp8x2(
                        make_float2(v[q].z * inv, v[q].w * inv),
                        __NV_SATFINITE, __NV_E4M3);
                    w[q] = (uint32_t)p01 | ((uint32_t)p23 << 16);
                }
                uint4 o4;
                o4.x = w[0]; o4.y = w[1]; o4.z = w[2]; o4.w = w[3];
                *reinterpret_cast<uint4*>(
                    g_l8 + (size_t)row * DIM + lane * 16) = o4;
            }
            __syncthreads();
            if (tid == 0) {
                __threadfence();
                const int cnt = (SEQ - 1 - c) / NNORM + 1;
                atomicAdd(&g_ready[b], cnt);
            }
        }
    }

    // ---------------- job loop ----------------
    for (;;) {
        if (tid == 0) job_s = atomicAdd(&g_ticket, 1);
        __syncthreads();
        const int ticket = job_s;
        if (ticket >= TOTTICK) {
            if (tid == 0) {
                const int old = atomicAdd(&g_exit, 1);
                if (old == NPERS - 1) {   // last exiter: reset for graph replay
                    g_ticket = 0; g_exit = 0; g_cnt = 0;
                    #pragma unroll
                    for (int b2 = 0; b2 < BATCH; ++b2) {
                        g_ready[b2] = 0;
                        g_dcnt[b2]  = 0;
                        for (int k2 = 0; k2 < NTILE; ++k2) g_fin[b2][k2] = 0;
                    }
                }
            }
            break;
        }

        if (ticket >= TOTJOBS) {
            // ================= finalize job (tail tickets) =================
            const int f  = ticket - TOTJOBS;     // 0..127
            const int bi = f / NTILE;
            const int k  = f - bi * NTILE;
            if (tid == 0) {
                while (ld_acquire(&g_fin[bi][k]) < 16) __nanosleep(64);
                if (k == 0)
                    while (ld_acquire(&g_dcnt[bi]) < NTILE) __nanosleep(64);
            }
            __syncthreads();

            const int r   = tid >> 1;        // row 0..127
            const int sub = tid & 1;
            const int nrow = (k < 8) ? 9 : 8;
            float seT = 0.f;
            #pragma unroll
            for (int u = 0; u < 8; ++u) {
                const int s = sub * 8 + u;   // 0..15
                seT += (s < nrow) ? g_rse[bi][k][s][r]
                                  : g_cse[bi][k][s - nrow][r];
            }
            seT += __shfl_xor_sync(0xffffffffu, seT, 1);

            float contrib = (sub == 0)
                ? (float)(SEQ - 1) * (SHIFT + logf(seT)) : 0.f;

            if (k == 0) {
                // batch analytic-rowsum term over 256 threads:
                // each owns components tid and tid+256 of c_b.
                float c1 = 0.f, c2 = 0.f;
                #pragma unroll
                for (int p = 0; p < NTILE * 2; ++p) {
                    c1 += g_cpart[bi][p][tid];
                    c2 += g_cpart[bi][p][tid + 256];
                }
                contrib += (SHIFT * (float)SEQ) * (1.0f / 256.0f)
                         - (c1 * c1 + c2 * c2) * INV256;
            }

            #pragma unroll
            for (int o = 2; o < 32; o <<= 1)
                contrib += __shfl_xor_sync(0xffffffffu, contrib, o);
            contrib += __shfl_xor_sync(0xffffffffu, contrib, 1);
            if (lane == 0) ws[wid] = contrib;
            __syncthreads();
            if (tid == 0) {
                float v = 0.f;
                #pragma unroll
                for (int w2 = 0; w2 < 8; ++w2) v += ws[w2];
                g_partials[bi * NTILE + k] = v;
                __threadfence();
                const int old = atomicAdd(&g_cnt, 1);
                flag_s = (old == NBLK - 1) ? 1 : 0;
            }
            __syncthreads();

            if (flag_s) {      // last finalize partial: deterministic final sum
                if (tid < 128) {
                    __threadfence();
                    float v = __ldcg(&g_partials[tid]);
                    #pragma unroll
                    for (int o = 16; o > 0; o >>= 1)
                        v += __shfl_xor_sync(0xffffffffu, v, o);
                    if ((tid & 31) == 0) ws[tid >> 5] = v;
                }
                __syncthreads();
                if (tid == 0)
                    out[0] = (ws[0] + ws[1] + ws[2] + ws[3])
                           * (LAMBDA / ((float)BATCH * (float)SEQ * (float)SEQ));
            }
            __syncthreads();   // protect ws/flag_s before next ticket
            continue;
        }

        // ================= GEMM job =================
        const int bi = ticket / NJOBS;
        const int jx = ticket - bi * NJOBS;
        int it, m;
        if (jx < 72) { it = jx / 9; m = jx % 9; }
        else { const int t2 = jx - 72; it = 8 + t2 / 8; m = t2 % 8; }
        const int j = (it + m) & 15;

        if (tid == 0)
            while (ld_acquire(&g_ready[bi]) < SEQ) __nanosleep(64);
        __syncthreads();

        const uint8_t* __restrict__ base = g_l8 + (size_t)bi * SEQ * DIM;
        const uint8_t* __restrict__ Ab   = base + (size_t)(it * BM) * DIM;
        const uint8_t* __restrict__ Bb   = base + (size_t)(j * BN) * DIM;

        auto load_stage = [&](int stage, int kp) {
            const uint32_t sbase = sb + stage * 4 * CTILE_B;
            #pragma unroll
            for (int u = 0; u < 8; ++u) {
                const int p  = tid + u * 256;
                const int ch = p >> 9;
                const int rem = p & 511;
                const int r = rem >> 2, c = rem & 3;
                const uint8_t* src = (ch < 2 ? Ab : Bb)
                    + (size_t)r * DIM + kp * 128 + (ch & 1) * 64 + c * 16;
                CP16(sbase + ch * CTILE_B + r * RSTRIDE + c * 16, src);
            }
            CP_COMMIT();
        };

        load_stage(0, 0);

        float acc[2][8][4];
        #pragma unroll
        for (int mt = 0; mt < 2; ++mt)
            #pragma unroll
            for (int nt = 0; nt < 8; ++nt)
                #pragma unroll
                for (int i = 0; i < 4; ++i) acc[mt][nt][i] = 0.f;

        for (int kp = 0; kp < NKP; ++kp) {
            if (kp + 1 < NKP) {
                load_stage((kp + 1) & 1, kp + 1);
                CP_WAIT(1);
            } else {
                CP_WAIT(0);
            }
            __syncthreads();

            #pragma unroll
            for (int cc = 0; cc < 2; ++cc) {
                const uint32_t abase = sb + ((kp & 1) * 4 + cc) * CTILE_B;
                const uint32_t bbase = sb + ((kp & 1) * 4 + 2 + cc) * CTILE_B;
                #pragma unroll
                for (int ks = 0; ks < 2; ++ks) {
                    uint32_t af[2][4];
                    #pragma unroll
                    for (int mt = 0; mt < 2; ++mt)
                        ldsm4(af[mt], abase
                              + (warp_m * 32 + mt * 16 + lrow) * RSTRIDE
                              + ks * 32 + lsel * 16);
                    uint32_t bx[4][4];
                    #pragma unroll
                    for (int q = 0; q < 4; ++q)
                        ldsm4(bx[q], bbase
                              + (warp_n * 64 + q * 16 + lrow) * RSTRIDE
                              + ks * 32 + lsel * 16);
                    #pragma unroll
                    for (int mt = 0; mt < 2; ++mt)
                        #pragma unroll
                        for (int nt = 0; nt < 8; ++nt) {
                            const int q = nt >> 1, e = nt & 1;
                            mma16832(acc[mt][nt], af[mt], bx[q][e], bx[q][e + 2]);
                        }
                }
            }

            // fused column-sum partials (diagonal jobs only)
            if (m == 0) {
                const int half = tid >> 7;
                const int col  = tid & 127;
                const size_t off = (size_t)((kp & 1) * 4 + (col >> 6)) * CTILE_B
                                 + (size_t)(half * 64) * RSTRIDE + (col & 63);
                float s = 0.f;
                #pragma unroll 8
                for (int r2 = 0; r2 < 64; ++r2)
                    s += fp8_to_f32((uint8_t)smem[off + (size_t)r2 * RSTRIDE]);
                g_cpart[bi][it * 2 + half][kp * 128 + col] = s;
            }
            __syncthreads();
        }

        // fused two-sided epilogue (sumexp only; v = acc/256)
        float se[4];
        #pragma unroll
        for (int s = 0; s < 4; ++s) se[s] = 0.f;

        if (m == 0) {
            #pragma unroll
            for (int mt = 0; mt < 2; ++mt)
                #pragma unroll
                for (int nt = 0; nt < 8; ++nt)
                    #pragma unroll
                    for (int i = 0; i < 4; ++i) {
                        const int lr = warp_m * 32 + mt * 16 + (i >> 1) * 8 + g;
                        const int lc = warp_n * 64 + nt * 8 + tig * 2 + (i & 1);
                        if (lr != lc)
                            se[mt * 2 + (i >> 1)] +=
                                __expf(fmaf(acc[mt][nt][i], INV256, -SHIFT));
                    }
        } else {
            float cse[16];
            #pragma unroll
            for (int q = 0; q < 16; ++q) cse[q] = 0.f;
            #pragma unroll
            for (int mt = 0; mt < 2; ++mt)
                #pragma unroll
                for (int nt = 0; nt < 8; ++nt)
                    #pragma unroll
                    for (int i = 0; i < 4; ++i) {
                        const float e =
                            __expf(fmaf(acc[mt][nt][i], INV256, -SHIFT));
                        se[mt * 2 + (i >> 1)] += e;
                        cse[nt * 2 + (i & 1)] += e;
                    }
            #pragma unroll
            for (int q = 0; q < 16; ++q) {
                #pragma unroll
                for (int o = 4; o < 32; o <<= 1)
                    cse[q] += __shfl_xor_sync(0xffffffffu, cse[q], o);
            }
            if (lane < 4) {
                #pragma unroll
                for (int nt = 0; nt < 8; ++nt)
                    #pragma unroll
                    for (int b2 = 0; b2 < 2; ++b2)
                        smc[wid][nt * 8 + lane * 2 + b2] = cse[nt * 2 + b2];
            }
        }

        #pragma unroll
        for (int s = 0; s < 4; ++s) {
            #pragma unroll
            for (int o = 1; o < 4; o <<= 1)
                se[s] += __shfl_xor_sync(0xffffffffu, se[s], o);
        }
        if (tig == 0) {
            #pragma unroll
            for (int s = 0; s < 4; ++s) se_red[wid][g][s] = se[s];
        }
        __syncthreads();

        if (tid < BM) {
            const int wm = tid >> 5;
            const int gg = (tid >> 2) & 7;
            const int ss = tid & 3;
            const int row = wm * 32 + (ss >> 1) * 16 + (ss & 1) * 8 + gg;
            g_rse[bi][it][m][row] =
                se_red[wm * 2][gg][ss] + se_red[wm * 2 + 1][gg][ss];
        } else if (m > 0) {
            const int t2 = tid - BM;
            const int wn = t2 >> 6, lc = t2 & 63;
            float cs = 0.f;
            #pragma unroll
            for (int wm = 0; wm < 4; ++wm) cs += smc[wm * 2 + wn][lc];
            g_cse[bi][j][m - 1][t2] = cs;
        }
        __syncthreads();

        // publish contributions (fenced)
        if (tid == 0) {
            __threadfence();
            atomicAdd(&g_fin[bi][it], 1);
            if (m > 0) atomicAdd(&g_fin[bi][j], 1);
            else       atomicAdd(&g_dcnt[bi], 1);
        }
    }
}

extern "C" void kernel_launch(void* const* d_in, const int* in_sizes, int n_in,
                              void* d_out, int out_size) {
    (void)in_sizes; (void)n_in; (void)out_size;
    const float* x = (const float*)d_in[0];
    float* out = (float*)d_out;

    cudaFuncSetAttribute(fused_all_kernel,
                         cudaFuncAttributeMaxDynamicSharedMemorySize, SMEM_TOTAL);

    fused_all_kernel<<<NPERS, 256, SMEM_TOTAL>>>(x, out);
}

// round 17
// speedup vs baseline: 1.1528x; 1.0606x over previous
#include <cuda_runtime.h>
#include <cuda_bf16.h>
#include <cuda_fp8.h>
#include <cstdint>
#include <math.h>

#define BATCH 8
#define SEQ   2048
#define DIM   512
#define BM    128
#define BN    128
#define NKP   4
#define NTILE (SEQ / BM)
#define NBLK  (BATCH * NTILE)
#define NFIN  (NBLK * 2)             // finalize half-block partials
#define NJOBS 136                    // GEMM jobs per batch
#define TOTJOBS (NJOBS * BATCH)      // 1088
#define NPERS 296                    // persistent CTAs (2 per SM)
#define NNORM 148                    // normalizer-role CTAs

#define SCALE8     50.59644256f
#define INV256     0.00390625f
#define SHIFT      10.0f
#define LAMBDA     0.5f

#define RSTRIDE    80
#define CTILE_B    (BM * RSTRIDE)
#define SMEM_TOTAL (8 * CTILE_B)

__device__ uint8_t g_l8[BATCH * SEQ * DIM];
__device__ float g_rse[BATCH][NTILE][9][BM];
__device__ float g_cse[BATCH][NTILE][8][BM];
__device__ float g_cpart[BATCH][NTILE * 2][DIM];
__device__ float g_partials[NFIN];
__device__ int   g_cnt;
__device__ int   g_ticket;
__device__ int   g_ready[BATCH];

__device__ __forceinline__ uint32_t smem_u32(const void* p) {
    uint32_t a;
    asm("{ .reg .u64 t; cvta.to.shared.u64 t, %1; cvt.u32.u64 %0, t; }"
        : "=r"(a) : "l"(p));
    return a;
}
__device__ __forceinline__ int ld_acquire(const int* p) {
    int v;
    asm volatile("ld.acquire.gpu.global.b32 %0, [%1];" : "=r"(v) : "l"(p));
    return v;
}
#define CP16(d, s) \
    asm volatile("cp.async.cg.shared.global [%0], [%1], 16;" :: "r"(d), "l"(s))
#define CP_COMMIT() asm volatile("cp.async.commit_group;" ::: "memory")
#define CP_WAIT(n)  asm volatile("cp.async.wait_group %0;" :: "n"(n) : "memory")

__device__ __forceinline__ void ldsm4(uint32_t* r, uint32_t addr) {
    asm volatile("ldmatrix.sync.aligned.m8n8.x4.shared.b16 {%0,%1,%2,%3}, [%4];"
                 : "=r"(r[0]), "=r"(r[1]), "=r"(r[2]), "=r"(r[3]) : "r"(addr));
}
__device__ __forceinline__ void mma16832(float* d, const uint32_t* a,
                                         uint32_t b0, uint32_t b1) {
    asm volatile(
        "mma.sync.aligned.m16n8k32.row.col.f32.e4m3.e4m3.f32 "
        "{%0,%1,%2,%3}, {%4,%5,%6,%7}, {%8,%9}, {%0,%1,%2,%3};"
        : "+f"(d[0]), "+f"(d[1]), "+f"(d[2]), "+f"(d[3])
        : "r"(a[0]), "r"(a[1]), "r"(a[2]), "r"(a[3]), "r"(b0), "r"(b1));
}
__device__ __forceinline__ float fp8_to_f32(uint8_t b) {
    __half_raw h = __nv_cvt_fp8_to_halfraw((__nv_fp8_storage_t)b, __NV_E4M3);
    return __half2float(*reinterpret_cast<__half*>(&h));
}

// ---------------------------------------------------------------------------
// Kernel 1 (persistent): role A (blockIdx<148) normalizes batches then joins
// the GEMM ticket loop; role B runs GEMM jobs from the start, spinning on the
// per-batch ready counter. Diagonal jobs emit fused column-sum partials.
// (Round-14 structure — best measured configuration.)
// ---------------------------------------------------------------------------
__global__ void __launch_bounds__(256, 2) fused_all_kernel(
        const float* __restrict__ x) {
    extern __shared__ char smem[];
    const uint32_t sb  = smem_u32(smem);
    const int tid  = threadIdx.x;
    const int wid  = tid >> 5;
    const int lane = tid & 31;
    const int warp_m = wid >> 1;
    const int warp_n = wid & 1;

    const int g    = lane >> 2;
    const int tig  = lane & 3;
    const int lrow = lane & 15;
    const int lsel = (lane >> 4) & 1;

    __shared__ int   job_s;
    __shared__ float smc[8][64];
    __shared__ float se_red[8][8][4];

    // ---------------- role A: normalize ----------------
    if (blockIdx.x < NNORM) {
        const int c = blockIdx.x;
        for (int b = 0; b < BATCH; ++b) {
            for (int idx = c + NNORM * wid; idx < SEQ; idx += NNORM * 8) {
                const int row = b * SEQ + idx;
                const float4* __restrict__ xr =
                    reinterpret_cast<const float4*>(x + (size_t)row * DIM)
                    + lane * 4;
                float4 v[4];
                float ss = 0.f;
                #pragma unroll
                for (int q = 0; q < 4; ++q) {
                    v[q] = xr[q];
                    ss = fmaf(v[q].x, v[q].x, ss);
                    ss = fmaf(v[q].y, v[q].y, ss);
                    ss = fmaf(v[q].z, v[q].z, ss);
                    ss = fmaf(v[q].w, v[q].w, ss);
                }
                #pragma unroll
                for (int o = 16; o > 0; o >>= 1)
                    ss += __shfl_xor_sync(0xffffffffu, ss, o);
                const float inv = SCALE8 / fmaxf(sqrtf(ss), 1e-8f);
                uint32_t w[4];
                #pragma unroll
                for (int q = 0; q < 4; ++q) {
                    const __nv_fp8x2_storage_t p01 = __nv_cvt_float2_to_fp8x2(
                        make_float2(v[q].x * inv, v[q].y * inv),
                        __NV_SATFINITE, __NV_E4M3);
                    const __nv_fp8x2_storage_t p23 = __nv_cvt_float2_to_fp8x2(
                        make_float2(v[q].z * inv, v[q].w * inv),
                        __NV_SATFINITE, __NV_E4M3);
                    w[q] = (uint32_t)p01 | ((uint32_t)p23 << 16);
                }
                uint4 o4;
                o4.x = w[0]; o4.y = w[1]; o4.z = w[2]; o4.w = w[3];
                *reinterpret_cast<uint4*>(
                    g_l8 + (size_t)row * DIM + lane * 16) = o4;
            }
            __syncthreads();
            if (tid == 0) {
                __threadfence();
                const int cnt = (SEQ - 1 - c) / NNORM + 1;
                atomicAdd(&g_ready[b], cnt);
            }
        }
    }

    // ---------------- GEMM job loop (both roles) ----------------
    for (;;) {
        if (tid == 0) {
            const int job = atomicAdd(&g_ticket, 1);
            job_s = job;
            if (job < TOTJOBS) {
                const int bi = job / NJOBS;
                while (ld_acquire(&g_ready[bi]) < SEQ) __nanosleep(64);
            }
        }
        __syncthreads();
        const int job = job_s;
        if (job >= TOTJOBS) break;

        const int bi = job / NJOBS;
        const int jx = job - bi * NJOBS;
        int it, m;
        if (jx < 72) { it = jx / 9; m = jx % 9; }
        else { const int t2 = jx - 72; it = 8 + t2 / 8; m = t2 % 8; }
        const int j = (it + m) & 15;

        const uint8_t* __restrict__ base = g_l8 + (size_t)bi * SEQ * DIM;
        const uint8_t* __restrict__ Ab   = base + (size_t)(it * BM) * DIM;
        const uint8_t* __restrict__ Bb   = base + (size_t)(j * BN) * DIM;

        auto load_stage = [&](int stage, int kp) {
            const uint32_t sbase = sb + stage * 4 * CTILE_B;
            #pragma unroll
            for (int u = 0; u < 8; ++u) {
                const int p  = tid + u * 256;
                const int ch = p >> 9;
                const int rem = p & 511;
                const int r = rem >> 2, c = rem & 3;
                const uint8_t* src = (ch < 2 ? Ab : Bb)
                    + (size_t)r * DIM + kp * 128 + (ch & 1) * 64 + c * 16;
                CP16(sbase + ch * CTILE_B + r * RSTRIDE + c * 16, src);
            }
            CP_COMMIT();
        };

        load_stage(0, 0);

        float acc[2][8][4];
        #pragma unroll
        for (int mt = 0; mt < 2; ++mt)
            #pragma unroll
            for (int nt = 0; nt < 8; ++nt)
                #pragma unroll
                for (int i = 0; i < 4; ++i) acc[mt][nt][i] = 0.f;

        for (int kp = 0; kp < NKP; ++kp) {
            if (kp + 1 < NKP) {
                load_stage((kp + 1) & 1, kp + 1);
                CP_WAIT(1);
            } else {
                CP_WAIT(0);
            }
            __syncthreads();

            #pragma unroll
            for (int cc = 0; cc < 2; ++cc) {
                const uint32_t abase = sb + ((kp & 1) * 4 + cc) * CTILE_B;
                const uint32_t bbase = sb + ((kp & 1) * 4 + 2 + cc) * CTILE_B;
                #pragma unroll
                for (int ks = 0; ks < 2; ++ks) {
                    uint32_t af[2][4];
                    #pragma unroll
                    for (int mt = 0; mt < 2; ++mt)
                        ldsm4(af[mt], abase
                              + (warp_m * 32 + mt * 16 + lrow) * RSTRIDE
                              + ks * 32 + lsel * 16);
                    uint32_t bx[4][4];
                    #pragma unroll
                    for (int q = 0; q < 4; ++q)
                        ldsm4(bx[q], bbase
                              + (warp_n * 64 + q * 16 + lrow) * RSTRIDE
                              + ks * 32 + lsel * 16);
                    #pragma unroll
                    for (int mt = 0; mt < 2; ++mt)
                        #pragma unroll
                        for (int nt = 0; nt < 8; ++nt) {
                            const int q = nt >> 1, e = nt & 1;
                            mma16832(acc[mt][nt], af[mt], bx[q][e], bx[q][e + 2]);
                        }
                }
            }

            // fused column-sum partials (diagonal jobs only)
            if (m == 0) {
                const int half = tid >> 7;
                const int col  = tid & 127;
                const size_t off = (size_t)((kp & 1) * 4 + (col >> 6)) * CTILE_B
                                 + (size_t)(half * 64) * RSTRIDE + (col & 63);
                float s = 0.f;
                #pragma unroll 8
                for (int r2 = 0; r2 < 64; ++r2)
                    s += fp8_to_f32((uint8_t)smem[off + (size_t)r2 * RSTRIDE]);
                g_cpart[bi][it * 2 + half][kp * 128 + col] = s;
            }
            __syncthreads();
        }

        // fused two-sided epilogue (sumexp only; v = acc/256)
        float se[4];
        #pragma unroll
        for (int s = 0; s < 4; ++s) se[s] = 0.f;

        if (m == 0) {
            #pragma unroll
            for (int mt = 0; mt < 2; ++mt)
                #pragma unroll
                for (int nt = 0; nt < 8; ++nt)
                    #pragma unroll
                    for (int i = 0; i < 4; ++i) {
                        const int lr = warp_m * 32 + mt * 16 + (i >> 1) * 8 + g;
                        const int lc = warp_n * 64 + nt * 8 + tig * 2 + (i & 1);
                        if (lr != lc)
                            se[mt * 2 + (i >> 1)] +=
                                __expf(fmaf(acc[mt][nt][i], INV256, -SHIFT));
                    }
        } else {
            float cse[16];
            #pragma unroll
            for (int q = 0; q < 16; ++q) cse[q] = 0.f;
            #pragma unroll
            for (int mt = 0; mt < 2; ++mt)
                #pragma unroll
                for (int nt = 0; nt < 8; ++nt)
                    #pragma unroll
                    for (int i = 0; i < 4; ++i) {
                        const float e =
                            __expf(fmaf(acc[mt][nt][i], INV256, -SHIFT));
                        se[mt * 2 + (i >> 1)] += e;
                        cse[nt * 2 + (i & 1)] += e;
                    }
            #pragma unroll
            for (int q = 0; q < 16; ++q) {
                #pragma unroll
                for (int o = 4; o < 32; o <<= 1)
                    cse[q] += __shfl_xor_sync(0xffffffffu, cse[q], o);
            }
            if (lane < 4) {
                #pragma unroll
                for (int nt = 0; nt < 8; ++nt)
                    #pragma unroll
                    for (int b2 = 0; b2 < 2; ++b2)
                        smc[wid][nt * 8 + lane * 2 + b2] = cse[nt * 2 + b2];
            }
        }

        #pragma unroll
        for (int s = 0; s < 4; ++s) {
            #pragma unroll
            for (int o = 1; o < 4; o <<= 1)
                se[s] += __shfl_xor_sync(0xffffffffu, se[s], o);
        }
        if (tig == 0) {
            #pragma unroll
            for (int s = 0; s < 4; ++s) se_red[wid][g][s] = se[s];
        }
        __syncthreads();

        if (tid < BM) {
            const int wm = tid >> 5;
            const int gg = (tid >> 2) & 7;
            const int ss = tid & 3;
            const int row = wm * 32 + (ss >> 1) * 16 + (ss & 1) * 8 + gg;
            g_rse[bi][it][m][row] =
                se_red[wm * 2][gg][ss] + se_red[wm * 2 + 1][gg][ss];
        } else if (m > 0) {
            const int t2 = tid - BM;
            const int wn = t2 >> 6, lc = t2 & 63;
            float cs = 0.f;
            #pragma unroll
            for (int wm = 0; wm < 4; ++wm) cs += smc[wm * 2 + wn][lc];
            g_cse[bi][j][m - 1][t2] = cs;
        }
        __syncthreads();        // protect smc/se_red/job_s before next job
    }
}

// ---------------------------------------------------------------------------
// Kernel 2: finalize, HALF-BLOCK granularity (grid 32x8 = 256 blocks, 256
// threads, 4 threads/row, 4 unrolled independent slot loads each). Block
// (k==0, half==0) adds the batch term SHIFT*SEQ - |c_b|^2/256. Elected tail
// reduces 256 partials and resets counters for graph replay.
// ---------------------------------------------------------------------------
__global__ void __launch_bounds__(256, 2) finalize_kernel(float* __restrict__ out) {
    const int kh   = blockIdx.x;            // 0..31
    const int b    = blockIdx.y;
    const int k    = kh >> 1;
    const int half = kh & 1;
    const int tid  = threadIdx.x;           // 0..255
    const int r    = half * 64 + (tid >> 2);
    const int sub  = tid & 3;

    __shared__ float ws[8];
    __shared__ int   flag;

    const int nrow = (k < 8) ? 9 : 8;
    float seT = 0.f;
    #pragma unroll
    for (int u = 0; u < 4; ++u) {
        const int s = sub * 4 + u;          // 0..15, independent loads
        seT += (s < nrow) ? g_rse[b][k][s][r]
                          : g_cse[b][k][s - nrow][r];
    }
    #pragma unroll
    for (int o = 1; o < 4; o <<= 1)
        seT += __shfl_xor_sync(0xffffffffu, seT, o);

    float contrib = (sub == 0)
        ? (float)(SEQ - 1) * (SHIFT + logf(seT)) : 0.f;

    if (k == 0 && half == 0) {
        // batch analytic-rowsum term: thread owns comps tid and tid+256
        float c1 = 0.f, c2 = 0.f;
        #pragma unroll
        for (int p = 0; p < NTILE * 2; ++p) {
            c1 += g_cpart[b][p][tid];
            c2 += g_cpart[b][p][tid + 256];
        }
        contrib += (SHIFT * (float)SEQ) * (1.0f / 256.0f)
                 - (c1 * c1 + c2 * c2) * INV256;
    }

    #pragma unroll
    for (int o = 1; o < 32; o <<= 1)
        contrib += __shfl_xor_sync(0xffffffffu, contrib, o);
    if ((tid & 31) == 0) ws[tid >> 5] = contrib;
    __syncthreads();
    if (tid == 0) {
        float v = 0.f;
        #pragma unroll
        for (int w2 = 0; w2 < 8; ++w2) v += ws[w2];
        g_partials[(b * NTILE + k) * 2 + half] = v;
        __threadfence();
        const int t = atomicAdd(&g_cnt, 1);
        flag = (t == NFIN - 1) ? 1 : 0;
    }
    __syncthreads();

    if (flag) {
        __threadfence();
        float v = __ldcg(&g_partials[tid]);     // 256 partials, 1 per thread
        #pragma unroll
        for (int o = 16; o > 0; o >>= 1)
            v += __shfl_xor_sync(0xffffffffu, v, o);
        if ((tid & 31) == 0) ws[tid >> 5] = v;
        __syncthreads();
        if (tid == 0) {
            float total = 0.f;
            #pragma unroll
            for (int w2 = 0; w2 < 8; ++w2) total += ws[w2];
            out[0] = total * (LAMBDA / ((float)BATCH * (float)SEQ * (float)SEQ));
            g_cnt = 0;
            g_ticket = 0;
            #pragma unroll
            for (int b2 = 0; b2 < BATCH; ++b2) g_ready[b2] = 0;
        }
    }
}

extern "C" void kernel_launch(void* const* d_in, const int* in_sizes, int n_in,
                              void* d_out, int out_size) {
    (void)in_sizes; (void)n_in; (void)out_size;
    const float* x = (const float*)d_in[0];
    float* out = (float*)d_out;

    cudaFuncSetAttribute(fused_all_kernel,
                         cudaFuncAttributeMaxDynamicSharedMemorySize, SMEM_TOTAL);

    fused_all_kernel<<<NPERS, 256, SMEM_TOTAL>>>(x);
    finalize_kernel<<<dim3(NTILE * 2, BATCH), 256>>>(out);
}